// round 15
// baseline (speedup 1.0000x reference)
#include <cuda_runtime.h>
#include <math_constants.h>

// Problem constants (NB, LQ, LK, DK, DV = 16, 384, 384, 64, 64)
#define NB 16
#define LQ 384
#define LK 384
#define DK 64
#define DV 64
#define INV_TEMP 0.125f  // 1 / TEMPERATURE, TEMPERATURE = 8.0

// Scratch for attn probabilities in case the harness output only holds `output`.
__device__ float g_attn_scratch[NB * LQ * LK];

// ---------------------------------------------------------------------------
// Single-loop fused kernel (R12 structure, WIN at 98.6us / 615 MB ideal
// traffic). R12's residual: DRAM 74.7% with issue=46% — per-iteration
// serialized latency (4 chained SHFLs ~104cyc + 2 expf + 5-deep rescale) per
// 16 streamed bytes. This round: TWO k-rows per iteration (12 iters):
//   - the two 4-shfl dot chains are independent -> pipelined, ~half the
//     serialized latency per row;
//   - ONE shared online-softmax rescale for both rows (mn=max(m,s0,s1)):
//     halves the rescale FFMAs and cuts expf from 2 to 1.5 per row;
//   - 2 back-to-back streaming loads per iteration -> deeper MLP.
// Grid 6144 x 256 is load-bearing: one-row blocks keep K L2/L1-warm
// (continuous re-touch), measured 615 MB total DRAM traffic in R12.
// ---------------------------------------------------------------------------
__global__ __launch_bounds__(256, 6)
void fused_kernel(const float* __restrict__ q,
                  const float* __restrict__ k,
                  const float* __restrict__ rpv,
                  float* __restrict__ out,
                  float* __restrict__ attn_ext)
{
    __shared__ float4 sq4[DK / 4];   // q row, 256 B
    __shared__ float  sa[LK];        // raw scores (already * INV_TEMP), 1.5 KB
    __shared__ float4 rbuf[256];     // acc reduction, 4 KB
    __shared__ float  rm[256];       // running-max reduction, 1 KB
    __shared__ float  rz[256];       // running-sum reduction, 1 KB
    __shared__ float  red[2];        // broadcast (m_final, 1/Z_final)

    float* attn = attn_ext ? attn_ext : g_attn_scratch;

    const int nq  = blockIdx.x;            // n*LQ + q
    const int n   = nq / LQ;
    const int tid = threadIdx.x;
    const int d4  = tid & 15;              // float4 column (K-dot AND stream)
    const int kk  = tid >> 4;              // half-warp id == k-slice start

    if (tid < DK / 4) {
        sq4[tid] = reinterpret_cast<const float4*>(q + (size_t)nq * DK)[tid];
    }
    __syncthreads();
    const float4 qv = sq4[d4];

    const float4* kb   = reinterpret_cast<const float4*>(
        k + (size_t)n * LK * DK);
    const float4* base = reinterpret_cast<const float4*>(
        rpv + (size_t)nq * LK * DV);

    float4 acc = make_float4(0.f, 0.f, 0.f, 0.f);
    float  m   = -CUDART_INF_F;
    float  Z   = 0.f;

#pragma unroll 3
    for (int i = 0; i < LK / 32; i++) {          // 12 iterations, 2 rows each
        const int k0 = kk + 32 * i;              // row pair: k0, k0+16
        const int k1 = k0 + 16;

        // Streaming value loads (DRAM, evict-first) — both issued up front.
        const float4 v0 = __ldcs(&base[k0 * (DV / 4) + d4]);
        const float4 v1 = __ldcs(&base[k1 * (DV / 4) + d4]);
        // K loads (L2/L1-warm).
        const float4 kv0 = kb[k0 * (DK / 4) + d4];
        const float4 kv1 = kb[k1 * (DK / 4) + d4];

        // Two cooperative dots; independent shfl chains pipeline together.
        float s0 = qv.x * kv0.x + qv.y * kv0.y + qv.z * kv0.z + qv.w * kv0.w;
        float s1 = qv.x * kv1.x + qv.y * kv1.y + qv.z * kv1.z + qv.w * kv1.w;
        s0 += __shfl_xor_sync(0xFFFFFFFFu, s0, 1);
        s1 += __shfl_xor_sync(0xFFFFFFFFu, s1, 1);
        s0 += __shfl_xor_sync(0xFFFFFFFFu, s0, 2);
        s1 += __shfl_xor_sync(0xFFFFFFFFu, s1, 2);
        s0 += __shfl_xor_sync(0xFFFFFFFFu, s0, 4);
        s1 += __shfl_xor_sync(0xFFFFFFFFu, s1, 4);
        s0 += __shfl_xor_sync(0xFFFFFFFFu, s0, 8);
        s1 += __shfl_xor_sync(0xFFFFFFFFu, s1, 8);
        s0 *= INV_TEMP;
        s1 *= INV_TEMP;
        if (d4 == 0) { sa[k0] = s0; sa[k1] = s1; }   // park for epilogue

        // Shared online-softmax update for the pair.
        // First iter: m=-inf -> sc=0; e0,e1 finite: exact.
        const float mn = fmaxf(m, fmaxf(s0, s1));
        const float sc = __expf(m - mn);
        const float e0 = __expf(s0 - mn);
        const float e1 = __expf(s1 - mn);
        acc.x = acc.x * sc + e0 * v0.x + e1 * v1.x;
        acc.y = acc.y * sc + e0 * v0.y + e1 * v1.y;
        acc.z = acc.z * sc + e0 * v0.z + e1 * v1.z;
        acc.w = acc.w * sc + e0 * v0.w + e1 * v1.w;
        Z = Z * sc + e0 + e1;
        m = mn;
    }

    // Block reduction over the 16 k-slices, merging (m, Z, acc) with rescale.
    rbuf[tid] = acc;
    rm[tid]   = m;
    rz[tid]   = Z;
    __syncthreads();
#pragma unroll
    for (int s = 128; s >= 16; s >>= 1) {
        if (tid < s) {
            const float m1 = rm[tid], m2 = rm[tid + s];
            const float mn = fmaxf(m1, m2);
            const float a  = __expf(m1 - mn);
            const float b  = __expf(m2 - mn);
            float4 x = rbuf[tid];
            float4 y = rbuf[tid + s];
            x.x = x.x * a + y.x * b;
            x.y = x.y * a + y.y * b;
            x.z = x.z * a + y.z * b;
            x.w = x.w * a + y.w * b;
            rbuf[tid] = x;
            rz[tid]   = rz[tid] * a + rz[tid + s] * b;
            rm[tid]   = mn;
        }
        __syncthreads();
    }

    // tid 0..15 hold the final (m, Z, acc) for their d4. Write out row.
    if (tid < 16) {
        const float inv = 1.0f / rz[tid];
        float4 x = rbuf[tid];
        x.x *= inv; x.y *= inv; x.z *= inv; x.w *= inv;
        __stcs(reinterpret_cast<float4*>(out + (size_t)nq * DV) + tid, x);
        if (tid == 0) {
            red[0] = rm[0];
            red[1] = inv;       // rz identical across d4 (same score sequence)
        }
    }
    __syncthreads();

    // Epilogue: attn row = e^{s - m_final} / Z_final, coalesced.
    {
        const float mf  = red[0];
        const float inv = red[1];
        float* arow = attn + (size_t)nq * LK;
        __stcs(arow + tid, __expf(sa[tid] - mf) * inv);
        if (tid < LK - 256) {
            __stcs(arow + tid + 256, __expf(sa[tid + 256] - mf) * inv);
        }
    }
}

// ---------------------------------------------------------------------------
// Launch. Inputs (metadata order) = q, k, v, rel_pos, rel_pos_v.
// v and rel_pos are unused by the reference — never touched.
// Output layout: [output (NB*LQ*DV) | attn (NB*LQ*LK)] when out_size covers
// both (branch taken and passing since R3); otherwise attn -> scratch.
// ---------------------------------------------------------------------------
extern "C" void kernel_launch(void* const* d_in, const int* in_sizes, int n_in,
                              void* d_out, int out_size)
{
    const float* q   = (const float*)d_in[0];
    const float* k   = (const float*)d_in[1];
    const float* rpv = (const float*)d_in[4];
    float* out = (float*)d_out;

    const long long out_elems  = (long long)NB * LQ * DV;   // 393216
    const long long attn_elems = (long long)NB * LQ * LK;   // 2359296

    float* attn_ext = nullptr;  // null -> kernel falls back to g_attn_scratch
    if ((long long)out_size >= out_elems + attn_elems) {
        attn_ext = out + out_elems;
    }

    fused_kernel<<<NB * LQ, 256>>>(q, k, rpv, out, attn_ext);
}